// round 1
// baseline (speedup 1.0000x reference)
#include <cuda_runtime.h>

#define N_NODES 100000
#define N_EDGES 1600000
#define D 128
#define A_DIM 512
#define G_NUM 64

// ---------------- scratch (device globals; no allocation allowed) ----------------
__device__ float g_deg[N_NODES];
__device__ float g_dis[N_NODES];
__device__ float g_bufA[N_NODES * D];   // h1, then h2
__device__ float g_bufB[N_NODES * D];   // out1, then out2

// ---------------- degree / normalization ----------------
__global__ void k_deg_init() {
    int i = blockIdx.x * blockDim.x + threadIdx.x;
    if (i < N_NODES) g_deg[i] = 1.0f;   // self loop
}

__global__ void k_deg_acc(const int* __restrict__ dst) {
    int e = blockIdx.x * blockDim.x + threadIdx.x;
    if (e < N_EDGES) atomicAdd(&g_deg[dst[e]], 1.0f);
}

__global__ void k_dis() {
    int i = blockIdx.x * blockDim.x + threadIdx.x;
    if (i < N_NODES) g_dis[i] = rsqrtf(g_deg[i]);   // deg >= 1 always
}

// ---------------- h1 = x @ W1  (warp per node) ----------------
__global__ void k_h1(const float* __restrict__ x, const float* __restrict__ W1) {
    int node = (blockIdx.x * blockDim.x + threadIdx.x) >> 5;
    int lane = threadIdx.x & 31;
    if (node >= N_NODES) return;
    float x0 = x[node * 3 + 0];
    float x1 = x[node * 3 + 1];
    float x2 = x[node * 3 + 2];
    int c = lane * 4;
    float4 w0 = *(const float4*)(W1 + 0 * D + c);
    float4 w1 = *(const float4*)(W1 + 1 * D + c);
    float4 w2 = *(const float4*)(W1 + 2 * D + c);
    float4 r;
    r.x = x0 * w0.x + x1 * w1.x + x2 * w2.x;
    r.y = x0 * w0.y + x1 * w1.y + x2 * w2.y;
    r.z = x0 * w0.z + x1 * w1.z + x2 * w2.z;
    r.w = x0 * w0.w + x1 * w1.w + x2 * w2.w;
    *(float4*)(g_bufA + node * D + c) = r;
}

// ---------------- out init: out[i] = b + h[i] * dis[i]^2  (self-loop term) ----------------
__global__ void k_init_out(const float* __restrict__ h, const float* __restrict__ b,
                           float* __restrict__ out) {
    int idx = blockIdx.x * blockDim.x + threadIdx.x;   // float4 index
    if (idx >= N_NODES * (D / 4)) return;
    int node = idx >> 5;
    int c4   = idx & 31;
    float dv = g_dis[node];
    float d2 = dv * dv;
    float4 hv = ((const float4*)h)[idx];
    float4 bv = ((const float4*)b)[c4];
    float4 o;
    o.x = bv.x + hv.x * d2;
    o.y = bv.y + hv.y * d2;
    o.z = bv.z + hv.z * d2;
    o.w = bv.w + hv.w * d2;
    ((float4*)out)[idx] = o;
}

// ---------------- edge scatter: out[dst] += h[src] * dis[src]*dis[dst]  (warp per edge) ----------------
__global__ void k_scatter(const int* __restrict__ src, const int* __restrict__ dst,
                          const float* __restrict__ h, float* __restrict__ out) {
    int e = (int)((blockIdx.x * (unsigned)blockDim.x + threadIdx.x) >> 5);
    int lane = threadIdx.x & 31;
    if (e >= N_EDGES) return;
    int s = src[e];
    int d = dst[e];
    float nrm = g_dis[s] * g_dis[d];
    float4 v = ((const float4*)(h + s * D))[lane];
    float* o = out + d * D + lane * 4;
    atomicAdd(o + 0, v.x * nrm);
    atomicAdd(o + 1, v.y * nrm);
    atomicAdd(o + 2, v.z * nrm);
    atomicAdd(o + 3, v.w * nrm);
}

// ---------------- h2 = relu(out1) @ W2  (smem-staged W2, warp per row) ----------------
#define GEMM_THREADS 256
#define NODES_PER_WARP 8
#define NODES_PER_BLOCK 64   // 8 warps * 8 nodes

__global__ void k_gemm_relu(const float* __restrict__ in, const float* __restrict__ W2,
                            float* __restrict__ outp) {
    extern __shared__ float smem[];          // [D*D] W2 + [8*D] row buffers
    float* sW   = smem;                      // 16384 floats
    float* srow = smem + D * D;              // 8 * 128 floats
    int tid = threadIdx.x;

    // stage W2 into shared
    for (int i = tid; i < D * D / 4; i += GEMM_THREADS)
        ((float4*)sW)[i] = ((const float4*)W2)[i];
    __syncthreads();

    int warp = tid >> 5, lane = tid & 31;
    int base = blockIdx.x * NODES_PER_BLOCK + warp * NODES_PER_WARP;

#pragma unroll 1
    for (int n = 0; n < NODES_PER_WARP; n++) {
        int node = base + n;
        if (node >= N_NODES) break;          // warp-uniform
        float4 hv = ((const float4*)(in + node * D))[lane];
        hv.x = fmaxf(hv.x, 0.0f);
        hv.y = fmaxf(hv.y, 0.0f);
        hv.z = fmaxf(hv.z, 0.0f);
        hv.w = fmaxf(hv.w, 0.0f);
        ((float4*)(srow + warp * D))[lane] = hv;
        __syncwarp();

        float4 acc = make_float4(0.f, 0.f, 0.f, 0.f);
#pragma unroll 16
        for (int k = 0; k < D; k++) {
            float hk = srow[warp * D + k];
            float4 w = ((const float4*)(sW + k * D))[lane];
            acc.x += hk * w.x;
            acc.y += hk * w.y;
            acc.z += hk * w.z;
            acc.w += hk * w.w;
        }
        ((float4*)(outp + node * D))[lane] = acc;
        __syncwarp();
    }
}

// ---------------- mean pool + final linear (block per graph) ----------------
__device__ __forceinline__ int lower_bound_dev(const int* __restrict__ b, int n, int v) {
    int lo = 0, hi = n;
    while (lo < hi) {
        int m = (lo + hi) >> 1;
        if (b[m] < v) lo = m + 1; else hi = m;
    }
    return lo;
}

__global__ void k_pool(const float* __restrict__ h, const int* __restrict__ batch,
                       const float* __restrict__ Wf, const float* __restrict__ bf,
                       float* __restrict__ q) {
    __shared__ float se[D];
    __shared__ float stmp[256];
    int g = blockIdx.x;
    int tid = threadIdx.x;        // 256 threads
    int lo = lower_bound_dev(batch, N_NODES, g);
    int hi = lower_bound_dev(batch, N_NODES, g + 1);

    int c = tid & 127, half = tid >> 7;
    float sum = 0.0f;
    for (int r = lo + half; r < hi; r += 2)
        sum += h[r * D + c];
    stmp[tid] = sum;
    __syncthreads();
    if (half == 0) {
        float tot = stmp[c] + stmp[128 + c];
        float cnt = (float)(hi - lo);
        se[c] = tot / fmaxf(cnt, 1.0f);
    }
    __syncthreads();

    for (int a = tid; a < A_DIM; a += 256) {
        float acc = bf[a];
#pragma unroll 16
        for (int k = 0; k < D; k++)
            acc += se[k] * Wf[k * A_DIM + a];
        q[g * A_DIM + a] = acc;
    }
}

// ---------------- launch ----------------
extern "C" void kernel_launch(void* const* d_in, const int* in_sizes, int n_in,
                              void* d_out, int out_size) {
    const float* x     = (const float*)d_in[0];
    const int*   ei    = (const int*)  d_in[1];
    const int*   batch = (const int*)  d_in[2];
    const float* W1    = (const float*)d_in[3];
    const float* b1    = (const float*)d_in[4];
    const float* W2    = (const float*)d_in[5];
    const float* b2    = (const float*)d_in[6];
    const float* Wf    = (const float*)d_in[7];
    const float* bf    = (const float*)d_in[8];
    float* q = (float*)d_out;

    const int* src = ei;             // edge_index[0]
    const int* dst = ei + N_EDGES;   // edge_index[1]

    float *bufA, *bufB;
    cudaGetSymbolAddress((void**)&bufA, g_bufA);
    cudaGetSymbolAddress((void**)&bufB, g_bufB);

    // degree + normalization (shared by both layers)
    k_deg_init<<<(N_NODES + 255) / 256, 256>>>();
    k_deg_acc<<<(N_EDGES + 255) / 256, 256>>>(dst);
    k_dis<<<(N_NODES + 255) / 256, 256>>>();

    // layer 1
    k_h1<<<(N_NODES * 32 + 255) / 256, 256>>>(x, W1);
    k_init_out<<<(N_NODES * (D / 4) + 255) / 256, 256>>>(bufA, b1, bufB);
    {
        long long threads = (long long)N_EDGES * 32;
        int blocks = (int)((threads + 255) / 256);
        k_scatter<<<blocks, 256>>>(src, dst, bufA, bufB);
    }

    // layer 2: h2 = relu(out1) @ W2
    int gemm_smem = (D * D + 8 * D) * (int)sizeof(float);   // 69632 B
    cudaFuncSetAttribute(k_gemm_relu, cudaFuncAttributeMaxDynamicSharedMemorySize, gemm_smem);
    k_gemm_relu<<<(N_NODES + NODES_PER_BLOCK - 1) / NODES_PER_BLOCK, GEMM_THREADS, gemm_smem>>>(bufB, W2, bufA);

    k_init_out<<<(N_NODES * (D / 4) + 255) / 256, 256>>>(bufA, b2, bufB);
    {
        long long threads = (long long)N_EDGES * 32;
        int blocks = (int)((threads + 255) / 256);
        k_scatter<<<blocks, 256>>>(src, dst, bufA, bufB);
    }

    // mean pool + final linear
    k_pool<<<G_NUM, 256>>>(bufB, batch, Wf, bf, q);
}

// round 2
// speedup vs baseline: 3.2074x; 3.2074x over previous
#include <cuda_runtime.h>

#define N_NODES 100000
#define N_EDGES 1600000
#define D 128
#define A_DIM 512
#define G_NUM 64
#define SCAN_BLK 1024
#define SCAN_NB ((N_NODES + SCAN_BLK - 1) / SCAN_BLK)   // 98

// ---------------- scratch (device globals; no allocation allowed) ----------------
__device__ float g_dis[N_NODES];
__device__ int   g_cnt[N_NODES];
__device__ int   g_incl[N_NODES];
__device__ int   g_bsum[128];
__device__ int   g_boff[128];
__device__ int   g_rowptr[N_NODES + 1];
__device__ int   g_cursor[N_NODES];
__device__ int2  g_adj[N_EDGES];            // {src, __float_as_int(norm)}
__device__ float g_bufA[N_NODES * D];
__device__ float g_bufB[N_NODES * D];

// ---------------- CSR build ----------------
__global__ void k_zero_cnt() {
    int i = blockIdx.x * blockDim.x + threadIdx.x;
    if (i < N_NODES) g_cnt[i] = 0;
}

__global__ void k_hist(const int* __restrict__ dst) {
    int e = blockIdx.x * blockDim.x + threadIdx.x;
    if (e < N_EDGES) atomicAdd(&g_cnt[dst[e]], 1);
}

__global__ void k_scan1() {
    __shared__ int sh[SCAN_BLK];
    int i = blockIdx.x * SCAN_BLK + threadIdx.x;
    int v = (i < N_NODES) ? g_cnt[i] : 0;
    sh[threadIdx.x] = v;
    __syncthreads();
    for (int off = 1; off < SCAN_BLK; off <<= 1) {
        int t = (threadIdx.x >= off) ? sh[threadIdx.x - off] : 0;
        __syncthreads();
        sh[threadIdx.x] += t;
        __syncthreads();
    }
    if (i < N_NODES) g_incl[i] = sh[threadIdx.x];
    if (threadIdx.x == SCAN_BLK - 1) g_bsum[blockIdx.x] = sh[SCAN_BLK - 1];
}

__global__ void k_scan2() {   // single block, 128 threads
    __shared__ int sh[128];
    int v = (threadIdx.x < SCAN_NB) ? g_bsum[threadIdx.x] : 0;
    sh[threadIdx.x] = v;
    __syncthreads();
    for (int off = 1; off < 128; off <<= 1) {
        int t = (threadIdx.x >= off) ? sh[threadIdx.x - off] : 0;
        __syncthreads();
        sh[threadIdx.x] += t;
        __syncthreads();
    }
    g_boff[threadIdx.x] = sh[threadIdx.x] - v;   // exclusive
}

__global__ void k_scan3() {
    int i = blockIdx.x * blockDim.x + threadIdx.x;
    if (i >= N_NODES) return;
    int c = g_cnt[i];
    int excl = g_incl[i] - c + g_boff[i >> 10];
    g_rowptr[i] = excl;
    g_cursor[i] = excl;
    if (i == N_NODES - 1) g_rowptr[N_NODES] = excl + c;
    g_dis[i] = rsqrtf((float)(c + 1));   // +1 self loop
}

__global__ void k_fill(const int* __restrict__ src, const int* __restrict__ dst) {
    int e = blockIdx.x * blockDim.x + threadIdx.x;
    if (e >= N_EDGES) return;
    int s = src[e];
    int d = dst[e];
    float nm = g_dis[s] * g_dis[d];
    int p = atomicAdd(&g_cursor[d], 1);
    g_adj[p] = make_int2(s, __float_as_int(nm));
}

// ---------------- h1 = x @ W1  (warp per node) ----------------
__global__ void k_h1(const float* __restrict__ x, const float* __restrict__ W1) {
    int node = (blockIdx.x * blockDim.x + threadIdx.x) >> 5;
    int lane = threadIdx.x & 31;
    if (node >= N_NODES) return;
    float x0 = x[node * 3 + 0];
    float x1 = x[node * 3 + 1];
    float x2 = x[node * 3 + 2];
    int c = lane * 4;
    float4 w0 = *(const float4*)(W1 + 0 * D + c);
    float4 w1 = *(const float4*)(W1 + 1 * D + c);
    float4 w2 = *(const float4*)(W1 + 2 * D + c);
    float4 r;
    r.x = x0 * w0.x + x1 * w1.x + x2 * w2.x;
    r.y = x0 * w0.y + x1 * w1.y + x2 * w2.y;
    r.z = x0 * w0.z + x1 * w1.z + x2 * w2.z;
    r.w = x0 * w0.w + x1 * w1.w + x2 * w2.w;
    *(float4*)(g_bufA + node * D + c) = r;
}

// ---------------- gather conv: out[d] = b + h[d]*dis[d]^2 + sum_in norm*h[s] ----------------
__global__ void k_gather(const float* __restrict__ h, const float* __restrict__ b,
                         float* __restrict__ out) {
    int node = (int)((blockIdx.x * (unsigned)blockDim.x + threadIdx.x) >> 5);
    int lane = threadIdx.x & 31;
    if (node >= N_NODES) return;
    int lo = g_rowptr[node];
    int hi = g_rowptr[node + 1];
    float dv = g_dis[node];
    float d2 = dv * dv;
    float4 hv = ((const float4*)(h + (size_t)node * D))[lane];
    float4 bv = ((const float4*)b)[lane];
    float4 acc;
    acc.x = bv.x + hv.x * d2;
    acc.y = bv.y + hv.y * d2;
    acc.z = bv.z + hv.z * d2;
    acc.w = bv.w + hv.w * d2;

    int i = lo;
    for (; i + 4 <= hi; i += 4) {
        int2 a0 = g_adj[i], a1 = g_adj[i + 1], a2 = g_adj[i + 2], a3 = g_adj[i + 3];
        float4 v0 = ((const float4*)(h + (size_t)a0.x * D))[lane];
        float4 v1 = ((const float4*)(h + (size_t)a1.x * D))[lane];
        float4 v2 = ((const float4*)(h + (size_t)a2.x * D))[lane];
        float4 v3 = ((const float4*)(h + (size_t)a3.x * D))[lane];
        float n0 = __int_as_float(a0.y), n1 = __int_as_float(a1.y);
        float n2 = __int_as_float(a2.y), n3 = __int_as_float(a3.y);
        acc.x += v0.x * n0 + v1.x * n1 + v2.x * n2 + v3.x * n3;
        acc.y += v0.y * n0 + v1.y * n1 + v2.y * n2 + v3.y * n3;
        acc.z += v0.z * n0 + v1.z * n1 + v2.z * n2 + v3.z * n3;
        acc.w += v0.w * n0 + v1.w * n1 + v2.w * n2 + v3.w * n3;
    }
    for (; i < hi; i++) {
        int2 a = g_adj[i];
        float nm = __int_as_float(a.y);
        float4 v = ((const float4*)(h + (size_t)a.x * D))[lane];
        acc.x += v.x * nm;
        acc.y += v.y * nm;
        acc.z += v.z * nm;
        acc.w += v.w * nm;
    }
    ((float4*)(out + (size_t)node * D))[lane] = acc;
}

// ---------------- h2 = relu(out1) @ W2  (4-row W-reuse, smem-staged W2) ----------------
#define GEMM_THREADS 256
#define ROWS_PER_PASS 4
#define NODES_PER_WARP 8
#define NODES_PER_BLOCK 64

__global__ void k_gemm_relu(const float* __restrict__ in, const float* __restrict__ W2,
                            float* __restrict__ outp) {
    extern __shared__ float smem[];
    float* sW   = smem;                       // D*D = 16384 floats (64KB)
    float* srow = smem + D * D;               // 8 warps * 4 rows * D (16KB)
    int tid = threadIdx.x;

    for (int i = tid; i < D * D / 4; i += GEMM_THREADS)
        ((float4*)sW)[i] = ((const float4*)W2)[i];
    __syncthreads();

    int warp = tid >> 5, lane = tid & 31;
    float* myrow = srow + warp * ROWS_PER_PASS * D;
    int base = blockIdx.x * NODES_PER_BLOCK + warp * NODES_PER_WARP;

#pragma unroll 1
    for (int c = 0; c < NODES_PER_WARP / ROWS_PER_PASS; c++) {
        int n0 = base + c * ROWS_PER_PASS;
#pragma unroll
        for (int r = 0; r < ROWS_PER_PASS; r++) {
            int node = n0 + r;
            float4 hv = make_float4(0.f, 0.f, 0.f, 0.f);
            if (node < N_NODES) hv = ((const float4*)(in + (size_t)node * D))[lane];
            hv.x = fmaxf(hv.x, 0.0f);
            hv.y = fmaxf(hv.y, 0.0f);
            hv.z = fmaxf(hv.z, 0.0f);
            hv.w = fmaxf(hv.w, 0.0f);
            ((float4*)(myrow + r * D))[lane] = hv;
        }
        __syncwarp();

        float4 a0 = make_float4(0.f,0.f,0.f,0.f), a1 = a0, a2 = a0, a3 = a0;
#pragma unroll 8
        for (int k = 0; k < D; k++) {
            float4 w = ((const float4*)(sW + k * D))[lane];
            float h0 = myrow[0 * D + k];
            float h1 = myrow[1 * D + k];
            float h2 = myrow[2 * D + k];
            float h3 = myrow[3 * D + k];
            a0.x += w.x * h0; a0.y += w.y * h0; a0.z += w.z * h0; a0.w += w.w * h0;
            a1.x += w.x * h1; a1.y += w.y * h1; a1.z += w.z * h1; a1.w += w.w * h1;
            a2.x += w.x * h2; a2.y += w.y * h2; a2.z += w.z * h2; a2.w += w.w * h2;
            a3.x += w.x * h3; a3.y += w.y * h3; a3.z += w.z * h3; a3.w += w.w * h3;
        }
        if (n0 + 0 < N_NODES) ((float4*)(outp + (size_t)(n0 + 0) * D))[lane] = a0;
        if (n0 + 1 < N_NODES) ((float4*)(outp + (size_t)(n0 + 1) * D))[lane] = a1;
        if (n0 + 2 < N_NODES) ((float4*)(outp + (size_t)(n0 + 2) * D))[lane] = a2;
        if (n0 + 3 < N_NODES) ((float4*)(outp + (size_t)(n0 + 3) * D))[lane] = a3;
        __syncwarp();
    }
}

// ---------------- mean pool + final linear (block per graph) ----------------
__device__ __forceinline__ int lower_bound_dev(const int* __restrict__ b, int n, int v) {
    int lo = 0, hi = n;
    while (lo < hi) {
        int m = (lo + hi) >> 1;
        if (b[m] < v) lo = m + 1; else hi = m;
    }
    return lo;
}

__global__ void k_pool(const float* __restrict__ h, const int* __restrict__ batch,
                       const float* __restrict__ Wf, const float* __restrict__ bf,
                       float* __restrict__ q) {
    __shared__ float se[D];
    __shared__ float stmp[256];
    int g = blockIdx.x;
    int tid = threadIdx.x;
    int lo = lower_bound_dev(batch, N_NODES, g);
    int hi = lower_bound_dev(batch, N_NODES, g + 1);

    int c = tid & 127, half = tid >> 7;
    float sum = 0.0f;
    for (int r = lo + half; r < hi; r += 2)
        sum += h[(size_t)r * D + c];
    stmp[tid] = sum;
    __syncthreads();
    if (half == 0) {
        float tot = stmp[c] + stmp[128 + c];
        float cnt = (float)(hi - lo);
        se[c] = tot / fmaxf(cnt, 1.0f);
    }
    __syncthreads();

    for (int a = tid; a < A_DIM; a += 256) {
        float acc = bf[a];
#pragma unroll 16
        for (int k = 0; k < D; k++)
            acc += se[k] * Wf[k * A_DIM + a];
        q[g * A_DIM + a] = acc;
    }
}

// ---------------- launch ----------------
extern "C" void kernel_launch(void* const* d_in, const int* in_sizes, int n_in,
                              void* d_out, int out_size) {
    const float* x     = (const float*)d_in[0];
    const int*   ei    = (const int*)  d_in[1];
    const int*   batch = (const int*)  d_in[2];
    const float* W1    = (const float*)d_in[3];
    const float* b1    = (const float*)d_in[4];
    const float* W2    = (const float*)d_in[5];
    const float* b2    = (const float*)d_in[6];
    const float* Wf    = (const float*)d_in[7];
    const float* bf    = (const float*)d_in[8];
    float* q = (float*)d_out;

    const int* src = ei;
    const int* dst = ei + N_EDGES;

    float *bufA, *bufB;
    cudaGetSymbolAddress((void**)&bufA, g_bufA);
    cudaGetSymbolAddress((void**)&bufB, g_bufB);

    // CSR build (+ degree norm)
    k_zero_cnt<<<(N_NODES + 255) / 256, 256>>>();
    k_hist<<<(N_EDGES + 255) / 256, 256>>>(dst);
    k_scan1<<<SCAN_NB, SCAN_BLK>>>();
    k_scan2<<<1, 128>>>();
    k_scan3<<<(N_NODES + 255) / 256, 256>>>();
    k_fill<<<(N_EDGES + 255) / 256, 256>>>(src, dst);

    // h1 = x @ W1 (runs while CSR builds have no data dependency on it)
    k_h1<<<(N_NODES * 32 + 255) / 256, 256>>>(x, W1);

    // layer 1 conv (gather)
    {
        long long threads = (long long)N_NODES * 32;
        int blocks = (int)((threads + 255) / 256);
        k_gather<<<blocks, 256>>>(bufA, b1, bufB);
    }

    // layer 2: h2 = relu(out1) @ W2
    int gemm_smem = (D * D + GEMM_THREADS / 32 * ROWS_PER_PASS * D) * (int)sizeof(float);
    cudaFuncSetAttribute(k_gemm_relu, cudaFuncAttributeMaxDynamicSharedMemorySize, gemm_smem);
    k_gemm_relu<<<(N_NODES + NODES_PER_BLOCK - 1) / NODES_PER_BLOCK, GEMM_THREADS, gemm_smem>>>(bufB, W2, bufA);

    // layer 2 conv (gather)
    {
        long long threads = (long long)N_NODES * 32;
        int blocks = (int)((threads + 255) / 256);
        k_gather<<<blocks, 256>>>(bufA, b2, bufB);
    }

    // mean pool + final linear
    k_pool<<<G_NUM, 256>>>(bufB, batch, Wf, bf, q);
}

// round 3
// speedup vs baseline: 5.7600x; 1.7958x over previous
#include <cuda_runtime.h>

#define N_NODES 100000
#define N_EDGES 1600000
#define D 128
#define A_DIM 512
#define G_NUM 64

// tall GEMM config
#define NBLK 250
#define KC 400
#define TK 25

// ---------------- scratch (device globals) ----------------
__device__ int   g_cnt[N_NODES];
__device__ float g_dis[N_NODES];
__device__ float g_agg3[N_NODES * 4];            // aggregated x (3 + pad)
__device__ float g_C[N_NODES * G_NUM];           // coefficient matrix [k][g]
__device__ float g_h1r[N_NODES * D];             // relu(conv1 out)
__device__ float g_part[NBLK * G_NUM * D];       // GEMM partials
__device__ float g_T[G_NUM * D];                 // reduced / mean-agg
__device__ float g_ge[G_NUM * D];                // graph embed after W2
__device__ float g_cntg[G_NUM];

// ---------------- f32x2 helpers ----------------
__device__ __forceinline__ unsigned long long packf2(float v) {
    unsigned long long r;
    unsigned int u = __float_as_uint(v);
    asm("mov.b64 %0, {%1, %1};" : "=l"(r) : "r"(u));
    return r;
}
__device__ __forceinline__ void fma2(unsigned long long& d, unsigned long long a,
                                     unsigned long long b) {
    asm("fma.rn.f32x2 %0, %1, %2, %0;" : "+l"(d) : "l"(a), "l"(b));
}

// ---------------- degree ----------------
__global__ void k_zero_cnt() {
    int i = blockIdx.x * blockDim.x + threadIdx.x;
    if (i < N_NODES) g_cnt[i] = 0;
}
__global__ void k_hist(const int* __restrict__ dst) {
    int e = blockIdx.x * blockDim.x + threadIdx.x;
    if (e < N_EDGES) atomicAdd(&g_cnt[dst[e]], 1);
}
// dis = rsqrt(deg), and init agg3 with self-loop term x[d]*dis^2
__global__ void k_dis_agg3(const float* __restrict__ x) {
    int i = blockIdx.x * blockDim.x + threadIdx.x;
    if (i >= N_NODES) return;
    float dv = rsqrtf((float)(g_cnt[i] + 1));
    g_dis[i] = dv;
    float d2 = dv * dv;
    float4 a;
    a.x = x[i * 3 + 0] * d2;
    a.y = x[i * 3 + 1] * d2;
    a.z = x[i * 3 + 2] * d2;
    a.w = 0.0f;
    ((float4*)g_agg3)[i] = a;
}

// zero C and set self term: C[d][batch[d]] = dis[d]^2
__global__ void k_zeroC_self(const int* __restrict__ batch) {
    int idx = blockIdx.x * blockDim.x + threadIdx.x;   // float4 index
    if (idx >= N_NODES * (G_NUM / 4)) return;
    int node = idx >> 4;           // 16 float4 per row
    int gbase = (idx & 15) * 4;
    int b = batch[node];
    float dv = g_dis[node];
    float d2 = dv * dv;
    float4 v;
    v.x = (gbase + 0 == b) ? d2 : 0.0f;
    v.y = (gbase + 1 == b) ? d2 : 0.0f;
    v.z = (gbase + 2 == b) ? d2 : 0.0f;
    v.w = (gbase + 3 == b) ? d2 : 0.0f;
    ((float4*)g_C)[idx] = v;
}

// per-edge: agg3[dst] += norm * x[src];  C[src][batch[dst]] += norm
__global__ void k_edge(const int* __restrict__ src, const int* __restrict__ dst,
                       const int* __restrict__ batch, const float* __restrict__ x) {
    int e = blockIdx.x * blockDim.x + threadIdx.x;
    if (e >= N_EDGES) return;
    int s = src[e];
    int d = dst[e];
    float nm = g_dis[s] * g_dis[d];
    int bd = batch[d];
    atomicAdd(&g_C[s * G_NUM + bd], nm);
    float x0 = x[s * 3 + 0], x1 = x[s * 3 + 1], x2 = x[s * 3 + 2];
    atomicAdd(&g_agg3[d * 4 + 0], nm * x0);
    atomicAdd(&g_agg3[d * 4 + 1], nm * x1);
    atomicAdd(&g_agg3[d * 4 + 2], nm * x2);
}

// h1r = relu(agg3 @ W1 + b1)   (warp per node)
__global__ void k_l1post(const float* __restrict__ W1, const float* __restrict__ b1) {
    int node = (int)((blockIdx.x * (unsigned)blockDim.x + threadIdx.x) >> 5);
    int lane = threadIdx.x & 31;
    if (node >= N_NODES) return;
    float4 a = ((const float4*)g_agg3)[node];
    int c = lane * 4;
    float4 w0 = *(const float4*)(W1 + 0 * D + c);
    float4 w1 = *(const float4*)(W1 + 1 * D + c);
    float4 w2 = *(const float4*)(W1 + 2 * D + c);
    float4 bv = *(const float4*)(b1 + c);
    float4 r;
    r.x = fmaxf(bv.x + a.x * w0.x + a.y * w1.x + a.z * w2.x, 0.0f);
    r.y = fmaxf(bv.y + a.x * w0.y + a.y * w1.y + a.z * w2.y, 0.0f);
    r.z = fmaxf(bv.z + a.x * w0.z + a.y * w1.z + a.z * w2.z, 0.0f);
    r.w = fmaxf(bv.w + a.x * w0.w + a.y * w1.w + a.z * w2.w, 0.0f);
    *(float4*)(g_h1r + (size_t)node * D + c) = r;
}

// nodes per graph via binary search on sorted batch
__global__ void k_cntg(const int* __restrict__ batch) {
    int g = threadIdx.x;
    if (g >= G_NUM) return;
    int lo = 0, hi = N_NODES;
    while (lo < hi) { int m = (lo + hi) >> 1; if (batch[m] < g) lo = m + 1; else hi = m; }
    int l0 = lo;
    lo = 0; hi = N_NODES;
    while (lo < hi) { int m = (lo + hi) >> 1; if (batch[m] < g + 1) lo = m + 1; else hi = m; }
    g_cntg[g] = fmaxf((float)(lo - l0), 1.0f);
}

// tall GEMM: part[blk][g][f] = sum_{k in chunk} C[k][g] * h1r[k][f]
__global__ __launch_bounds__(128) void k_gemmS() {
    __shared__ __align__(16) float sC[TK * G_NUM];    // 1600 floats
    __shared__ __align__(16) float sh[TK * D];        // 3200 floats
    int tid = threadIdx.x;
    int tg = tid >> 4;          // 8 groups of 8 g
    int tf = tid & 15;          // 16 groups of 8 f
    int g0 = tg * 8;
    int f0 = tf * 8;

    unsigned long long acc[8][4];
#pragma unroll
    for (int i = 0; i < 8; i++)
#pragma unroll
        for (int p = 0; p < 4; p++) acc[i][p] = 0ULL;

    int kbase = blockIdx.x * KC;
#pragma unroll 1
    for (int t = 0; t < KC / TK; t++) {
        int k0 = kbase + t * TK;
        const float4* Cg = (const float4*)(g_C + (size_t)k0 * G_NUM);
        const float4* hg = (const float4*)(g_h1r + (size_t)k0 * D);
        for (int i = tid; i < TK * G_NUM / 4; i += 128) ((float4*)sC)[i] = Cg[i];
        for (int i = tid; i < TK * D / 4; i += 128) ((float4*)sh)[i] = hg[i];
        __syncthreads();

#pragma unroll 1
        for (int kk = 0; kk < TK; kk++) {
            float4 ca = *(const float4*)(sC + kk * G_NUM + g0);
            float4 cb = *(const float4*)(sC + kk * G_NUM + g0 + 4);
            ulonglong2 ha = *(const ulonglong2*)(sh + kk * D + f0);
            ulonglong2 hb = *(const ulonglong2*)(sh + kk * D + f0 + 4);
            unsigned long long hp[4] = {ha.x, ha.y, hb.x, hb.y};
            unsigned long long cp[8];
            cp[0] = packf2(ca.x); cp[1] = packf2(ca.y);
            cp[2] = packf2(ca.z); cp[3] = packf2(ca.w);
            cp[4] = packf2(cb.x); cp[5] = packf2(cb.y);
            cp[6] = packf2(cb.z); cp[7] = packf2(cb.w);
#pragma unroll
            for (int i = 0; i < 8; i++)
#pragma unroll
                for (int p = 0; p < 4; p++) fma2(acc[i][p], cp[i], hp[p]);
        }
        __syncthreads();
    }

    float* base = g_part + (size_t)blockIdx.x * G_NUM * D;
#pragma unroll
    for (int i = 0; i < 8; i++)
#pragma unroll
        for (int p = 0; p < 4; p++)
            *(unsigned long long*)(base + (g0 + i) * D + f0 + p * 2) = acc[i][p];
}

// reduce partials and divide by counts -> g_T[g][f] (mean aggregate)
__global__ void k_reduce() {
    int i = blockIdx.x * blockDim.x + threadIdx.x;
    if (i >= G_NUM * D) return;
    float s = 0.0f;
    for (int b = 0; b < NBLK; b++) s += g_part[(size_t)b * G_NUM * D + i];
    g_T[i] = s / g_cntg[i / D];
}

// ge = T @ W2 + b2   (block per graph)
__global__ void k_pw(const float* __restrict__ W2, const float* __restrict__ b2) {
    __shared__ float st[D];
    int g = blockIdx.x;
    int j = threadIdx.x;    // 128
    st[j] = g_T[g * D + j];
    __syncthreads();
    float acc = b2[j];
#pragma unroll 16
    for (int f = 0; f < D; f++) acc += st[f] * W2[f * D + j];
    g_ge[g * D + j] = acc;
}

// q = ge @ Wf + bf   (block per graph, 256 threads, 2 outputs each)
__global__ void k_q(const float* __restrict__ Wf, const float* __restrict__ bf,
                    float* __restrict__ q) {
    __shared__ float st[D];
    int g = blockIdx.x;
    int tid = threadIdx.x;   // 256
    if (tid < D) st[tid] = g_ge[g * D + tid];
    __syncthreads();
#pragma unroll
    for (int h = 0; h < 2; h++) {
        int a = tid + h * 256;
        float acc = bf[a];
#pragma unroll 16
        for (int j = 0; j < D; j++) acc += st[j] * Wf[j * A_DIM + a];
        q[g * A_DIM + a] = acc;
    }
}

// ---------------- launch ----------------
extern "C" void kernel_launch(void* const* d_in, const int* in_sizes, int n_in,
                              void* d_out, int out_size) {
    const float* x     = (const float*)d_in[0];
    const int*   ei    = (const int*)  d_in[1];
    const int*   batch = (const int*)  d_in[2];
    const float* W1    = (const float*)d_in[3];
    const float* b1    = (const float*)d_in[4];
    const float* W2    = (const float*)d_in[5];
    const float* b2    = (const float*)d_in[6];
    const float* Wf    = (const float*)d_in[7];
    const float* bf    = (const float*)d_in[8];
    float* q = (float*)d_out;

    const int* src = ei;
    const int* dst = ei + N_EDGES;

    k_zero_cnt<<<(N_NODES + 255) / 256, 256>>>();
    k_hist<<<(N_EDGES + 255) / 256, 256>>>(dst);
    k_dis_agg3<<<(N_NODES + 255) / 256, 256>>>(x);
    k_zeroC_self<<<(N_NODES * (G_NUM / 4) + 255) / 256, 256>>>(batch);
    k_edge<<<(N_EDGES + 255) / 256, 256>>>(src, dst, batch, x);
    k_l1post<<<(N_NODES * 32 + 255) / 256, 256>>>(W1, b1);
    k_cntg<<<1, 64>>>(batch);
    k_gemmS<<<NBLK, 128>>>();
    k_reduce<<<(G_NUM * D + 255) / 256, 256>>>();
    k_pw<<<G_NUM, 128>>>(W2, b2);
    k_q<<<G_NUM, 256>>>(Wf, bf, q);
}